// round 11
// baseline (speedup 1.0000x reference)
#include <cuda_runtime.h>

#define BATCH 2048
#define NE    2048
#define NDIMS 128
#define SPEC_C 6.5f
#define LOG2E 1.4426950408889634f

#define TILE    128
#define DCHUNK  32
#define SXROW   264   // duplicated x row: 256 floats + 8 pad (16B-aligned stride)
#define SEROW   132   // e row: 128 + 4 pad

#define SMEM_FLOATS (DCHUNK * (SXROW + SEROW))
#define SMEM_BYTES  (SMEM_FLOATS * 4)

// Scratch (device globals: allocation-free rule)
__device__ float g_xs[BATCH * NDIMS];   // u = C*log2e * attn * X
__device__ float g_es[NE * NDIMS];      // v = C*log2e * attn * E
__device__ float g_sumx[BATCH];         // -sum_d u
__device__ float g_sume[NE];            // -sum_d v

// ---------------------------------------------------------------------------
// Pre-scale by C*log2e; row sums negated.
//   exp2-domain term per element: -|u-v| = 2*min(u,v) - u - v
// ---------------------------------------------------------------------------
__global__ void prep_kernel(const float* __restrict__ X,
                            const float* __restrict__ E,
                            const float* __restrict__ attn) {
    const int warp = threadIdx.x >> 5;
    const int lane = threadIdx.x & 31;
    const int row  = blockIdx.x * 8 + warp;

    const float* src  = blockIdx.y ? E : X;
    float*       dst  = blockIdx.y ? g_es : g_xs;
    float*       dsum = blockIdx.y ? g_sume : g_sumx;

    const float k = SPEC_C * LOG2E;
    float4 x = reinterpret_cast<const float4*>(src + (size_t)row * NDIMS)[lane];
    float4 a = reinterpret_cast<const float4*>(attn)[lane];
    float4 s = make_float4(k * x.x * a.x, k * x.y * a.y, k * x.z * a.z, k * x.w * a.w);
    reinterpret_cast<float4*>(dst + (size_t)row * NDIMS)[lane] = s;

    float t = (s.x + s.y) + (s.z + s.w);
    #pragma unroll
    for (int off = 16; off > 0; off >>= 1)
        t += __shfl_xor_sync(0xffffffffu, t, off);
    if (lane == 0) dsum[row] = -t;
}

__device__ __forceinline__ float ex2f(float x) {
    float r;
    asm("ex2.approx.ftz.f32 %0, %1;" : "=f"(r) : "f"(x));
    return r;
}

// low float of a b64 pair (register-pair alias; compiles to nothing or 1 MOV)
__device__ __forceinline__ float pair_lo(unsigned long long v) {
    float lo;
    asm("{\n\t.reg .f32 hi;\n\tmov.b64 {%0, hi}, %1;\n\t}" : "=f"(lo) : "l"(v));
    return lo;
}

// Packed abs-diff accumulate: (a0,a1) -= |(u,u) - (v0,v1)|
//   1x fma.rn.f32x2 (diff, fma pipe) + 2x scalar FADD with abs modifier (rt1).
__device__ __forceinline__ void abs_acc(float& a0, float& a1,
                                        unsigned long long u2,
                                        unsigned long long v2,
                                        unsigned long long neg1x2) {
    float t0, t1;
    asm("{\n\t"
        ".reg .b64 t;\n\t"
        "fma.rn.f32x2 t, %3, %4, %2;\n\t"   // t = u + v*(-1)
        "mov.b64 {%0, %1}, t;\n\t"
        "}" : "=f"(t0), "=f"(t1) : "l"(u2), "l"(v2), "l"(neg1x2));
    a0 -= fabsf(t0);
    a1 -= fabsf(t1);
}

// ---------------------------------------------------------------------------
// Main: 128x128 tile / block, 256 threads, 8x8 micro-tile, occ 2.
// x tile stored DUPLICATED in smem so (u_i,u_i) broadcast pairs arrive as b64
// halves of LDS.128 (no packing MOVs); e pairs are natural LDS.128 halves.
// Columns j0,j1: scalar min-form (alu FMNMX + fma FFMA-imm).
// Columns j2..j7: packed abs-form (fma2 + 2x FADD-abs).
// Per warp-d: 6 LDS + 110 math slots for 64 elements.
// ---------------------------------------------------------------------------
__global__ __launch_bounds__(256, 2)
void alcove_kernel(float* __restrict__ out) {
    extern __shared__ float smem[];
    float* sx2 = smem;                   // [DCHUNK][SXROW] duplicated x
    float* se  = smem + DCHUNK * SXROW;  // [DCHUNK][SEROW]

    const int tid = threadIdx.x;
    const int tx  = tid & 15;
    const int ty  = tid >> 4;
    const int b0  = blockIdx.y * TILE;
    const int e0  = blockIdx.x * TILE;

    const unsigned long long NEG1x2 = 0xBF800000BF800000ULL;  // (-1.f, -1.f)

    float accM[8][2];   // min-form columns j0, j1
    float accA[8][6];   // abs-form columns j2..j7
    #pragma unroll
    for (int i = 0; i < 8; ++i) {
        accM[i][0] = accM[i][1] = 0.f;
        #pragma unroll
        for (int j = 0; j < 6; ++j) accA[i][j] = 0.f;
    }

    // staging decomposition: thread -> (q = d-quad 0..7, r = row-within-32)
    const int q  = tid & 7;
    const int r  = tid >> 3;
    const int qh = q >> 1;

    const float* sxp = sx2 + ty * 8;   // duplicated: row i at float 2i
    const float* sep = se  + tx * 4;

    for (int dc = 0; dc < NDIMS; dc += DCHUNK) {
        __syncthreads();
        // Stage: 4 passes of 32 rows. x duplicated via STS.64 (v,v); e scalar STS.
        #pragma unroll
        for (int p = 0; p < 4; ++p) {
            const int row = r + p * 32;
            const float4 vx = *reinterpret_cast<const float4*>(
                &g_xs[(size_t)(b0 + row) * NDIMS + dc + q * 4]);
            const float4 ve = *reinterpret_cast<const float4*>(
                &g_es[(size_t)(e0 + row) * NDIMS + dc + q * 4]);
            const float xa[4] = {vx.x, vx.y, vx.z, vx.w};
            const float ea[4] = {ve.x, ve.y, ve.z, ve.w};
            #pragma unroll
            for (int s = 0; s < 4; ++s) {
                const int k = (s + qh) & 3;           // rotation: spreads banks
                const int d = q * 4 + k;
                *reinterpret_cast<float2*>(&sx2[d * SXROW + 2 * row]) =
                    make_float2(xa[k], xa[k]);
                se[d * SEROW + row] = ea[k];
            }
        }
        __syncthreads();

        #pragma unroll 4
        for (int d = 0; d < DCHUNK; ++d) {
            // duplicated x: 4x LDS.128 -> 8 broadcast pairs (b64 halves)
            const ulonglong2 xq0 = *reinterpret_cast<const ulonglong2*>(sxp + d * SXROW);
            const ulonglong2 xq1 = *reinterpret_cast<const ulonglong2*>(sxp + d * SXROW + 4);
            const ulonglong2 xq2 = *reinterpret_cast<const ulonglong2*>(sxp + d * SXROW + 128);
            const ulonglong2 xq3 = *reinterpret_cast<const ulonglong2*>(sxp + d * SXROW + 132);
            // e: 2x LDS.128 -> 2 scalars + 3 packed pairs
            const float4     ef0 = *reinterpret_cast<const float4*>(sep + d * SEROW);
            const ulonglong2 eq1 = *reinterpret_cast<const ulonglong2*>(sep + d * SEROW + 64);
            const unsigned long long p23 =
                *reinterpret_cast<const unsigned long long*>(&ef0.z);  // (v2,v3) reg pair
            const unsigned long long p45 = eq1.x;
            const unsigned long long p67 = eq1.y;

            const unsigned long long u2v[8] = {xq0.x, xq0.y, xq1.x, xq1.y,
                                               xq2.x, xq2.y, xq3.x, xq3.y};
            #pragma unroll
            for (int i = 0; i < 8; ++i) {
                const float ui = pair_lo(u2v[i]);
                // min-form j0, j1 (alu + fma)
                accM[i][0] = fmaf(fminf(ui, ef0.x), 2.0f, accM[i][0]);
                accM[i][1] = fmaf(fminf(ui, ef0.y), 2.0f, accM[i][1]);
                // abs-form j2..j7 (fma pipe: fma2 + FADD-abs x2 per pair)
                abs_acc(accA[i][0], accA[i][1], u2v[i], p23, NEG1x2);
                abs_acc(accA[i][2], accA[i][3], u2v[i], p45, NEG1x2);
                abs_acc(accA[i][4], accA[i][5], u2v[i], p67, NEG1x2);
            }
        }
    }

    // Epilogue.
    float nsu[8], nsv2[2];
    #pragma unroll
    for (int i = 0; i < 8; ++i) {
        const int ri = (i < 4) ? (ty * 4 + i) : (64 + ty * 4 + (i - 4));
        nsu[i] = g_sumx[b0 + ri];                 // = -Su
    }
    nsv2[0] = g_sume[e0 + tx * 4 + 0];            // = -Sv for j0, j1
    nsv2[1] = g_sume[e0 + tx * 4 + 1];

    #pragma unroll
    for (int i = 0; i < 8; ++i) {
        const int ri = (i < 4) ? (ty * 4 + i) : (64 + ty * 4 + (i - 4));
        float res[8];
        res[0] = ex2f(accM[i][0] + (nsu[i] + nsv2[0]));   // min-form
        res[1] = ex2f(accM[i][1] + (nsu[i] + nsv2[1]));
        #pragma unroll
        for (int j = 0; j < 6; ++j)                       // abs-form: arg complete
            res[2 + j] = ex2f(accA[i][j]);
        float* orow = out + (size_t)(b0 + ri) * NE + e0;
        *reinterpret_cast<float4*>(&orow[tx * 4])      = make_float4(res[0], res[1], res[2], res[3]);
        *reinterpret_cast<float4*>(&orow[64 + tx * 4]) = make_float4(res[4], res[5], res[6], res[7]);
    }
}

// ---------------------------------------------------------------------------
extern "C" void kernel_launch(void* const* d_in, const int* in_sizes, int n_in,
                              void* d_out, int out_size) {
    const float* X    = (const float*)d_in[0];  // (2048,128)
    const float* E    = (const float*)d_in[1];  // (2048,128)
    const float* attn = (const float*)d_in[2];  // (128,)
    float* out = (float*)d_out;                 // (2048,2048)

    cudaFuncSetAttribute(alcove_kernel,
                         cudaFuncAttributeMaxDynamicSharedMemorySize, SMEM_BYTES);

    dim3 gprep(BATCH / 8, 2);
    prep_kernel<<<gprep, 256>>>(X, E, attn);

    dim3 gmain(NE / TILE, BATCH / TILE);   // (16, 16) = 256 blocks
    alcove_kernel<<<gmain, 256, SMEM_BYTES>>>(out);
}